// round 17
// baseline (speedup 1.0000x reference)
#include <cuda_runtime.h>
#include <cuda_fp16.h>
#include <math.h>

// Problem constants (fixed by reference setup_inputs):
//   n = 100000 nodes, seq_len = 4, hidden = 128, n_edges = 1.6M
#define MAX_N      100000
#define HIDDEN     128
#define SEQ_STRIDE (4 * 128)   // floats per node in semantics

// Scratch (device globals; no allocations allowed).
__device__ float  g_sums[MAX_N * HIDDEN];   // 51.2 MB fp32 accumulators
__device__ float  g_cntf[MAX_N];            // per-target in-degree (float)
__device__ __half g_sem16[MAX_N * HIDDEN];  // fp16 copy of sem[:,0,:]
__device__ unsigned long long g_Wp[(HIDDEN / 2) * HIDDEN]; // k-pair-packed W
__device__ int    g_idx_is_64;              // 1 = int64 edge_index, 0 = int32

// ---------------------------------------------------------------------------
// f32x2 FMA (no packing movs anywhere in the hot loop).
// ---------------------------------------------------------------------------
__device__ __forceinline__ void fma_f32x2(unsigned long long& d,
                                          unsigned long long a,
                                          unsigned long long b) {
    asm("fma.rn.f32x2 %0, %1, %2, %0;" : "+l"(d) : "l"(a), "l"(b));
}
__device__ __forceinline__ float hsum_f32x2(unsigned long long v) {
    float lo, hi;
    asm("mov.b64 {%0, %1}, %2;" : "=f"(lo), "=f"(hi) : "l"(v));
    return lo + hi;
}

// ---------------------------------------------------------------------------
// Kernel 0: zero g_sums/g_cntf + pack W into k-pair layout + dtype probe.
// g_Wp[kp*128 + c] holds (W[2kp][c], W[2kp+1][c]) as a native 64-bit word.
// ---------------------------------------------------------------------------
__global__ void prep_kernel(const float* __restrict__ W,
                            const long long* __restrict__ ei64,
                            long long n, int n_nodes) {
    int tid = blockIdx.x * blockDim.x + threadIdx.x;
    int nt  = gridDim.x * blockDim.x;

    float4 z = make_float4(0.f, 0.f, 0.f, 0.f);
    float4* sums4 = (float4*)g_sums;
    const int n4 = n_nodes * (HIDDEN / 4);
    for (int i = tid; i < n4; i += nt) sums4[i] = z;
    for (int i = tid; i < n_nodes; i += nt) g_cntf[i] = 0.f;

    // Pack W: 64 kp x 128 c.
    for (int i = tid; i < (HIDDEN / 2) * HIDDEN; i += nt) {
        int kp = i >> 7;
        int c  = i & 127;
        float lo = __ldg(W + (2 * kp) * HIDDEN + c);
        float hi = __ldg(W + (2 * kp + 1) * HIDDEN + c);
        float2 p = make_float2(lo, hi);
        g_Wp[i] = *(unsigned long long*)&p;
    }

    if (blockIdx.x == 0 && threadIdx.x < 32) {
        int lane = threadIdx.x;
        int bad = 0;
        #pragma unroll
        for (int i = 0; i < 8; i++) {
            long long v = ei64[lane * 8 + i];
            if (v < 0 || v >= n) bad = 1;
        }
        unsigned m = __ballot_sync(0xFFFFFFFFu, bad);
        if (lane == 0) g_idx_is_64 = (m == 0u) ? 1 : 0;
    }
}

// ---------------------------------------------------------------------------
// Kernel 1: convert sem[:,0,:] fp32 -> fp16 (halves the random gather bytes).
// ---------------------------------------------------------------------------
__global__ void cvt_kernel(const float* __restrict__ sem, int n_nodes) {
    int tid = blockIdx.x * blockDim.x + threadIdx.x;
    int nt  = gridDim.x * blockDim.x;
    const int n_oct = n_nodes * (HIDDEN / 8);
    for (int i = tid; i < n_oct; i += nt) {
        int node = i >> 4;           // 16 octs of 8 floats per node
        int oct  = i & 15;
        const float4* src = (const float4*)(sem + (size_t)node * SEQ_STRIDE + oct * 8);
        float4 a = __ldg(src);
        float4 b = __ldg(src + 1);
        __half2 h[4];
        h[0] = __floats2half2_rn(a.x, a.y);
        h[1] = __floats2half2_rn(a.z, a.w);
        h[2] = __floats2half2_rn(b.x, b.y);
        h[3] = __floats2half2_rn(b.z, b.w);
        *(uint4*)(g_sem16 + (size_t)node * HIDDEN + oct * 8) = *(uint4*)h;
    }
}

// ---------------------------------------------------------------------------
// Kernel 2: scatter, 4 independent edges per warp (R14/R16 champion).
// ---------------------------------------------------------------------------
#define EPW 4   // edges per warp
__global__ void __launch_bounds__(256)
scatter_kernel(const void* __restrict__ ei_raw, int n_edges) {
    const int warp = (blockIdx.x * blockDim.x + threadIdx.x) >> 5;
    const int lane = threadIdx.x & 31;
    const int e0 = warp * EPW;
    if (e0 >= n_edges) return;

    const int m = min(EPW, n_edges - e0);

    int srcs[EPW], tgts[EPW];
    if (g_idx_is_64) {
        const longlong2* ei = (const longlong2*)ei_raw;
        #pragma unroll
        for (int u = 0; u < EPW; u++) {
            longlong2 p = __ldg(ei + e0 + (u < m ? u : 0));
            srcs[u] = (int)p.x; tgts[u] = (int)p.y;
        }
    } else {
        const int2* ei = (const int2*)ei_raw;
        #pragma unroll
        for (int u = 0; u < EPW; u++) {
            int2 p = __ldg(ei + e0 + (u < m ? u : 0));
            srcs[u] = p.x; tgts[u] = p.y;
        }
    }

    // 4 independent 256 B row loads (8 B/lane each).
    uint2 v[EPW];
    #pragma unroll
    for (int u = 0; u < EPW; u++)
        v[u] = __ldg((const uint2*)(g_sem16 + (size_t)srcs[u] * HIDDEN) + lane);

    #pragma unroll
    for (int u = 0; u < EPW; u++) {
        if (u < m) {
            float2 f0 = __half22float2(*(__half2*)&v[u].x);
            float2 f1 = __half22float2(*(__half2*)&v[u].y);
            float* dst = g_sums + (size_t)tgts[u] * HIDDEN + lane * 4;
            asm volatile("red.global.add.v4.f32 [%0], {%1, %2, %3, %4};"
                         :: "l"(dst), "f"(f0.x), "f"(f0.y), "f"(f1.x), "f"(f1.y)
                         : "memory");
        }
    }

    if (lane < m) atomicAdd(&g_cntf[tgts[lane]], 1.0f);
}

// ---------------------------------------------------------------------------
// Kernel 3: fused (sums @ W) / max(cnt,1) -> exact GELU -> out.
// TPB=128, thread owns 4 rows x 4 cols. Per kp (2 k-steps):
//   2x LDG.128 (pre-packed Wp k-pairs) + 4x broadcast LDS.64 (s k-pairs)
//   + 16 FFMA2, and ZERO packing movs (R16 measured ALU 52.9% from packs).
// ---------------------------------------------------------------------------
#define RPB 16
__global__ void __launch_bounds__(128)
gemm_mean_gelu_kernel(float* __restrict__ out, int n) {
    __shared__ float4 s4[RPB][HIDDEN / 4];
    const int r0 = blockIdx.x * RPB;
    const int t  = threadIdx.x;

    const float4 z = make_float4(0.f, 0.f, 0.f, 0.f);
    for (int i = t; i < RPB * (HIDDEN / 4); i += 128) {
        int r  = i >> 5;
        int kq = i & 31;
        int row = r0 + r;
        s4[r][kq] = (row < n)
            ? ((const float4*)(g_sums + (size_t)row * HIDDEN))[kq] : z;
    }
    __syncthreads();

    const int rg = t >> 5;          // row group 0..3 (rows rg*4 .. rg*4+3)
    const int c  = (t & 31) * 4;    // column base
    const unsigned long long* srow =
        (const unsigned long long*)&s4[rg * 4][0];   // rows rg*4.., 64 kp each

    unsigned long long acc2[4][4];  // [row][col], k-pair packed
    #pragma unroll
    for (int rr = 0; rr < 4; rr++)
        #pragma unroll
        for (int cc = 0; cc < 4; cc++) acc2[rr][cc] = 0ull;

    #pragma unroll 4
    for (int kp = 0; kp < HIDDEN / 2; kp++) {
        // W k-pairs for cols c..c+3: two 16 B loads, zero movs.
        const uint4 wa = __ldg((const uint4*)(g_Wp + kp * HIDDEN + c));
        const uint4 wb = __ldg((const uint4*)(g_Wp + kp * HIDDEN + c + 2));
        const unsigned long long w0 = *(const unsigned long long*)&wa.x;
        const unsigned long long w1 = *(const unsigned long long*)&wa.z;
        const unsigned long long w2 = *(const unsigned long long*)&wb.x;
        const unsigned long long w3 = *(const unsigned long long*)&wb.z;

        #pragma unroll
        for (int rr = 0; rr < 4; rr++) {
            // native 64-bit broadcast LDS of (s[r][2kp], s[r][2kp+1])
            unsigned long long sp = srow[rr * (HIDDEN / 2) + kp];
            fma_f32x2(acc2[rr][0], sp, w0);
            fma_f32x2(acc2[rr][1], sp, w1);
            fma_f32x2(acc2[rr][2], sp, w2);
            fma_f32x2(acc2[rr][3], sp, w3);
        }
    }

    #pragma unroll
    for (int rr = 0; rr < 4; rr++) {
        int row = r0 + rg * 4 + rr;
        if (row < n) {
            float inv = 1.0f / fmaxf(g_cntf[row], 1.0f);
            float4 o;
            o.x = hsum_f32x2(acc2[rr][0]) * inv;
            o.y = hsum_f32x2(acc2[rr][1]) * inv;
            o.z = hsum_f32x2(acc2[rr][2]) * inv;
            o.w = hsum_f32x2(acc2[rr][3]) * inv;
            // exact GELU: 0.5*x*(1 + erf(x/sqrt(2)))
            o.x = 0.5f * o.x * (1.0f + erff(o.x * 0.70710678118654752f));
            o.y = 0.5f * o.y * (1.0f + erff(o.y * 0.70710678118654752f));
            o.z = 0.5f * o.z * (1.0f + erff(o.z * 0.70710678118654752f));
            o.w = 0.5f * o.w * (1.0f + erff(o.w * 0.70710678118654752f));
            *(float4*)(out + (size_t)row * HIDDEN + c) = o;
        }
    }
}

// ---------------------------------------------------------------------------
// kernel_launch: prep -> cvt -> scatter -> gemm (gemm at ncu capture slot 3).
// All graph-capturable; no allocations.
// Input order (metadata): semantics, attention_masks (unused), W, edge_index.
// ---------------------------------------------------------------------------
extern "C" void kernel_launch(void* const* d_in, const int* in_sizes, int n_in,
                              void* d_out, int out_size) {
    const float* sem = (const float*)d_in[0];
    const float* W   = (const float*)d_in[2];
    const void*  ei  = d_in[3];
    float* out = (float*)d_out;

    const int n       = in_sizes[0] / SEQ_STRIDE;   // 100000
    const int n_edges = in_sizes[3] / 2;            // 1600000

    prep_kernel<<<400, 512>>>(W, (const long long*)ei, (long long)n, n);
    cvt_kernel<<<400, 512>>>(sem, n);

    const int epb = 8 * EPW;    // 8 warps/block
    scatter_kernel<<<(n_edges + epb - 1) / epb, 256>>>(ei, n_edges);

    int gb = (n + RPB - 1) / RPB;
    gemm_mean_gelu_kernel<<<gb, 128>>>(out, n);
}